// round 1
// baseline (speedup 1.0000x reference)
#include <cuda_runtime.h>
#include <math.h>

// N=200000, H=8, D=64  => rows = N*H = 1,600,000 ; floats = 102,400,000
// Each block: 16 rows. 256 threads = 16 rows x 16 float4 (64 floats/row).
// Grid = 1,600,000 / 16 = 100,000 blocks.

#define ROWS_PER_BLOCK 16
#define THREADS 256

__global__ __launch_bounds__(THREADS)
void emma_merge_kernel(const float4* __restrict__ x,
                       const float* __restrict__ max_a,
                       const float4* __restrict__ his_x,
                       const float* __restrict__ his_m,
                       const float* __restrict__ agg_n,
                       const float* __restrict__ inv_w,
                       float4* __restrict__ out)
{
    __shared__ float p_s[ROWS_PER_BLOCK];
    __shared__ float q_s[ROWS_PER_BLOCK];

    const int b = blockIdx.x;
    const int t = threadIdx.x;

    // One thread per row computes the scalars (2 expf per row total).
    if (t < ROWS_PER_BLOCK) {
        const int row = b * ROWS_PER_BLOCK + t;   // row in [0, N*H)
        const int n   = row >> 3;                 // H = 8
        const float iw   = __ldg(inv_w);
        const float beta = fminf(fmaxf(1.0f - iw * __ldg(&agg_n[n]), 0.0f), 1.0f);
        const float ma   = __ldg(&max_a[row]);
        const float hm   = __ldg(&his_m[row]);
        const float mm   = fmaxf(ma, hm);

        float dp = hm - ma > 0.0f ? 0.0f : hm - mm;  // hm - mm, stable
        dp = hm - mm;
        float dq = ma - mm;
        if (isnan(dp)) dp = -INFINITY;               // nan_to_num(..., nan=-inf)
        if (isnan(dq)) dq = -INFINITY;

        float p = expf(dp) * beta;
        float q = expf(dq);
        const float tt  = fmaxf(p + q, 1.0f);        // clamp_min_(1.0)
        const float inv = 1.0f / tt;
        p_s[t] = p * inv;
        q_s[t] = q * inv;
    }
    __syncthreads();

    // Vectorized streaming pass: thread t handles float4 #(t%16) of row (t/16).
    const int rl = t >> 4;                           // local row 0..15
    const float p = p_s[rl];
    const float q = q_s[rl];

    const long long idx = (long long)b * THREADS + t; // global float4 index
    const float4 xv = x[idx];
    const float4 hv = his_x[idx];
    float4 o;
    o.x = fmaf(hv.x, p, xv.x * q);
    o.y = fmaf(hv.y, p, xv.y * q);
    o.z = fmaf(hv.z, p, xv.z * q);
    o.w = fmaf(hv.w, p, xv.w * q);
    out[idx] = o;
}

extern "C" void kernel_launch(void* const* d_in, const int* in_sizes, int n_in,
                              void* d_out, int out_size)
{
    const float4* x     = (const float4*)d_in[0];
    const float*  max_a = (const float*) d_in[1];
    const float4* his_x = (const float4*)d_in[2];
    const float*  his_m = (const float*) d_in[3];
    const float*  agg_n = (const float*) d_in[4];
    const float*  inv_w = (const float*) d_in[5];
    float4*       out   = (float4*)      d_out;

    // rows = N*H derived from max_a element count; D = 64 floats = 16 float4
    const int rows   = in_sizes[1];                  // 1,600,000
    const int blocks = rows / ROWS_PER_BLOCK;        // 100,000

    emma_merge_kernel<<<blocks, THREADS>>>(x, max_a, his_x, his_m, agg_n, inv_w, out);
}

// round 2
// speedup vs baseline: 1.1228x; 1.1228x over previous
#include <cuda_runtime.h>
#include <math.h>

// N=200000, H=8, D=64  => rows = N*H = 1,600,000 ; float4s = 25,600,000
// Block: 64 rows = 1024 float4. 256 threads x 4 float4 each (strided by 256
// within the block for perfect coalescing). Grid = 25,000 blocks.

#define ROWS_PER_BLOCK 64
#define THREADS 256
#define V4_PER_BLOCK (ROWS_PER_BLOCK * 16)   // 1024
#define SEGS 4

__global__ __launch_bounds__(THREADS)
void emma_merge_kernel(const float4* __restrict__ x,
                       const float* __restrict__ max_a,
                       const float4* __restrict__ his_x,
                       const float* __restrict__ his_m,
                       const float* __restrict__ agg_n,
                       const float* __restrict__ inv_w,
                       float4* __restrict__ out)
{
    __shared__ float p_s[ROWS_PER_BLOCK];
    __shared__ float q_s[ROWS_PER_BLOCK];

    const int b = blockIdx.x;
    const int t = threadIdx.x;

    // One thread per row computes the per-row scalars (2 expf per row).
    if (t < ROWS_PER_BLOCK) {
        const int row = b * ROWS_PER_BLOCK + t;   // row in [0, N*H)
        const int n   = row >> 3;                 // H = 8
        const float iw   = __ldg(inv_w);
        const float beta = fminf(fmaxf(1.0f - iw * __ldg(&agg_n[n]), 0.0f), 1.0f);
        const float ma   = __ldg(&max_a[row]);
        const float hm   = __ldg(&his_m[row]);
        const float mm   = fmaxf(ma, hm);

        float dp = hm - mm;
        float dq = ma - mm;
        if (isnan(dp)) dp = -INFINITY;            // nan_to_num(..., nan=-inf)
        if (isnan(dq)) dq = -INFINITY;

        float p = expf(dp) * beta;
        float q = expf(dq);
        const float tt  = fmaxf(p + q, 1.0f);     // clamp_min_(1.0)
        const float inv = 1.0f / tt;
        p_s[t] = p * inv;
        q_s[t] = q * inv;
    }
    __syncthreads();

    const long long base = (long long)b * V4_PER_BLOCK;

    // Front-batch all 8 loads (4 x + 4 his_x) to maximize MLP.
    float4 xv[SEGS], hv[SEGS];
#pragma unroll
    for (int k = 0; k < SEGS; k++)
        xv[k] = x[base + t + k * THREADS];
#pragma unroll
    for (int k = 0; k < SEGS; k++)
        hv[k] = his_x[base + t + k * THREADS];

#pragma unroll
    for (int k = 0; k < SEGS; k++) {
        const int rl = (t + k * THREADS) >> 4;    // local row 0..63 (warp-broadcast)
        const float p = p_s[rl];
        const float q = q_s[rl];
        float4 o;
        o.x = fmaf(hv[k].x, p, xv[k].x * q);
        o.y = fmaf(hv[k].y, p, xv[k].y * q);
        o.z = fmaf(hv[k].z, p, xv[k].z * q);
        o.w = fmaf(hv[k].w, p, xv[k].w * q);
        // Streaming (evict-first) store: out is write-once, keep it out of L2's way.
        const float4* ptr = &out[base + t + k * THREADS];
        asm volatile("st.global.cs.v4.f32 [%0], {%1, %2, %3, %4};"
                     :: "l"(ptr), "f"(o.x), "f"(o.y), "f"(o.z), "f"(o.w)
                     : "memory");
    }
}

extern "C" void kernel_launch(void* const* d_in, const int* in_sizes, int n_in,
                              void* d_out, int out_size)
{
    const float4* x     = (const float4*)d_in[0];
    const float*  max_a = (const float*) d_in[1];
    const float4* his_x = (const float4*)d_in[2];
    const float*  his_m = (const float*) d_in[3];
    const float*  agg_n = (const float*) d_in[4];
    const float*  inv_w = (const float*) d_in[5];
    float4*       out   = (float4*)      d_out;

    const int rows   = in_sizes[1];               // 1,600,000
    const int blocks = rows / ROWS_PER_BLOCK;     // 25,000

    emma_merge_kernel<<<blocks, THREADS>>>(x, max_a, his_x, his_m, agg_n, inv_w, out);
}